// round 6
// baseline (speedup 1.0000x reference)
#include <cuda_runtime.h>
#include <cuda_bf16.h>
#include <math.h>

#define N_LEVELS 16
#define TBL (1u << 19)
#define BLOCK 128
#define NMAX (1 << 20)

struct Meta {
    float scale[N_LEVELS];
    int   res[N_LEVELS];
    unsigned hashed_mask;
};

// Transposed weights (input-major rows of 64): [wt1t 32*64 | wt2t 64*64 | wt3t 64*64 | w4 64]
__device__ float g_wt[32 * 64 + 64 * 64 + 64 * 64 + 64];
// Staged encoding, feature-major: g_enc[f * N + p], f = 2*level + d
__device__ float g_enc[(size_t)32 * NMAX];

__device__ __forceinline__ float softplus10(float v) {
    float t = 10.0f * v;
    float e = __expf(-fabsf(t));
    return (log1pf(e) + fmaxf(t, 0.0f)) * 0.1f;
}

__device__ __forceinline__ unsigned long long pack2(float a) {
    unsigned long long r;
    asm("mov.b64 %0, {%1, %1};" : "=l"(r) : "r"(__float_as_uint(a)));
    return r;
}

__device__ __forceinline__ void fma2(unsigned long long& acc,
                                     unsigned long long w,
                                     unsigned long long a) {
    asm("fma.rn.f32x2 %0, %1, %2, %0;" : "+l"(acc) : "l"(w), "l"(a));
}

__device__ __forceinline__ void unpack2(unsigned long long v, float& lo, float& hi) {
    unsigned ulo, uhi;
    asm("mov.b64 {%0, %1}, %2;" : "=r"(ulo), "=r"(uhi) : "l"(v));
    lo = __uint_as_float(ulo);
    hi = __uint_as_float(uhi);
}

__global__ void prep_weights(const float* __restrict__ W1,
                             const float* __restrict__ W2,
                             const float* __restrict__ W3,
                             const float* __restrict__ W4)
{
    const int tid = blockIdx.x * blockDim.x + threadIdx.x;
    for (int idx = tid; idx < 64 * 32; idx += gridDim.x * blockDim.x) {
        int j = idx >> 5, i = idx & 31;
        g_wt[i * 64 + j] = W1[idx];
    }
    for (int idx = tid; idx < 64 * 64; idx += gridDim.x * blockDim.x) {
        int j = idx >> 6, i = idx & 63;
        g_wt[32 * 64 + i * 64 + j] = W2[idx];
        g_wt[32 * 64 + 64 * 64 + i * 64 + j] = W3[idx];
    }
    if (tid < 64) g_wt[32 * 64 + 2 * 64 * 64 + tid] = W4[tid];
}

// ---------------- Kernel 1: hash-grid encoding -> g_enc (feature-major) -------------
__global__ void __launch_bounds__(256)
encode_kernel(const float* __restrict__ x, const float* __restrict__ grid,
              int N, Meta meta)
{
    const int p = blockIdx.x * 256 + threadIdx.x;
    if (p >= N) return;

    const float px = x[p * 3 + 0];
    const float py = x[p * 3 + 1];
    const float pz = x[p * 3 + 2];

#pragma unroll 4
    for (int l = 0; l < N_LEVELS; l++) {
        const float s = meta.scale[l];
        const int res = meta.res[l];
        const bool hashed = (meta.hashed_mask >> l) & 1u;

        float fx = fmaf(px, s, 0.5f);
        float fy = fmaf(py, s, 0.5f);
        float fz = fmaf(pz, s, 0.5f);
        float fx0 = floorf(fx), fy0 = floorf(fy), fz0 = floorf(fz);
        float rx = fx - fx0, ry = fy - fy0, rz = fz - fz0;
        int ix = (int)fx0, iy = (int)fy0, iz = (int)fz0;

        const float2* g = (const float2*)grid + (size_t)l * TBL;
        float a0 = 0.0f, a1 = 0.0f;

#pragma unroll
        for (int c = 0; c < 8; c++) {
            const int cx = c & 1, cy = (c >> 1) & 1, cz = (c >> 2) & 1;
            float w = (cx ? rx : 1.0f - rx) *
                      (cy ? ry : 1.0f - ry) *
                      (cz ? rz : 1.0f - rz);
            unsigned idx;
            if (hashed) {
                unsigned gx = (unsigned)(ix + cx);
                unsigned gy = (unsigned)(iy + cy);
                unsigned gz = (unsigned)(iz + cz);
                idx = (gx * 1u) ^ (gy * 2654435761u) ^ (gz * 805459861u);
                idx &= (TBL - 1u);
            } else {
                int gx = min(max(ix + cx, 0), res - 1);
                int gy = min(max(iy + cy, 0), res - 1);
                int gz = min(max(iz + cz, 0), res - 1);
                idx = (unsigned)(gx + res * (gy + res * gz));
            }
            float2 f = __ldg(&g[idx]);
            a0 = fmaf(w, f.x, a0);
            a1 = fmaf(w, f.y, a1);
        }
        g_enc[(size_t)(2 * l + 0) * N + p] = a0;   // coalesced across warp
        g_enc[(size_t)(2 * l + 1) * N + p] = a1;
    }
}

// ---------------- Kernel 2: MLP ----------------
// Each thread: 4 points x 16 outputs (its j-quarter). STRIDE = row stride of act source.
template <int NIN>
__device__ __forceinline__ void layer_accum_s(const float* __restrict__ wtq,
                                              const float* __restrict__ actp,
                                              size_t stride,
                                              unsigned long long* acc2) {
#pragma unroll
    for (int k = 0; k < 32; k++) acc2[k] = 0ull;
#pragma unroll 4
    for (int i = 0; i < NIN; i++) {
        float4 a = *(const float4*)(actp + (size_t)i * stride);
        unsigned long long a2[4];
        a2[0] = pack2(a.x); a2[1] = pack2(a.y);
        a2[2] = pack2(a.z); a2[3] = pack2(a.w);
        const ulonglong2* wr = (const ulonglong2*)(wtq + i * 64);
#pragma unroll
        for (int u = 0; u < 4; u++) {
            ulonglong2 w = __ldg(&wr[u]);
#pragma unroll
            for (int d = 0; d < 4; d++) {
                fma2(acc2[d * 8 + 2 * u + 0], w.x, a2[d]);
                fma2(acc2[d * 8 + 2 * u + 1], w.y, a2[d]);
            }
        }
    }
}

__device__ __forceinline__ void writeback_softplus(float* __restrict__ act,
                                                   const unsigned long long* acc2,
                                                   int q, int woff) {
#pragma unroll
    for (int k = 0; k < 8; k++) {
        float lo[4], hi[4];
#pragma unroll
        for (int d = 0; d < 4; d++) {
            float l, h;
            unpack2(acc2[d * 8 + k], l, h);
            lo[d] = softplus10(l);
            hi[d] = softplus10(h);
        }
        *(float4*)(act + (q * 16 + 2 * k + 0) * BLOCK + woff) =
            make_float4(lo[0], lo[1], lo[2], lo[3]);
        *(float4*)(act + (q * 16 + 2 * k + 1) * BLOCK + woff) =
            make_float4(hi[0], hi[1], hi[2], hi[3]);
    }
}

__global__ void __launch_bounds__(BLOCK)
mlp_kernel(float* __restrict__ out, int N)
{
    extern __shared__ float act[];   // [64][BLOCK], 32 KB

    const int tid  = threadIdx.x;
    const int w    = tid >> 5;
    const int lane = tid & 31;
    const int pidx = lane & 7;
    const int q    = lane >> 3;
    const int woff = w * 32 + 4 * pidx;
    const int pbase = blockIdx.x * BLOCK + woff;

    const float* wt1 = g_wt;
    const float* wt2 = g_wt + 32 * 64;
    const float* wt3 = g_wt + 32 * 64 + 64 * 64;
    const float* w4g = g_wt + 32 * 64 + 2 * 64 * 64;

    unsigned long long acc2[32];

    // Layer 1: act source = g_enc (global, feature-major, stride N)
    layer_accum_s<32>(wt1 + q * 16, g_enc + pbase, (size_t)N, acc2);
    writeback_softplus(act, acc2, q, woff);
    __syncwarp();

    layer_accum_s<64>(wt2 + q * 16, act + woff, BLOCK, acc2);
    writeback_softplus(act, acc2, q, woff);
    __syncwarp();

    layer_accum_s<64>(wt3 + q * 16, act + woff, BLOCK, acc2);

    float sdf[4] = {0.0f, 0.0f, 0.0f, 0.0f};
#pragma unroll
    for (int k = 0; k < 8; k++) {
        float w4a = __ldg(&w4g[q * 16 + 2 * k + 0]);
        float w4b = __ldg(&w4g[q * 16 + 2 * k + 1]);
#pragma unroll
        for (int d = 0; d < 4; d++) {
            float l, h;
            unpack2(acc2[d * 8 + k], l, h);
            sdf[d] = fmaf(softplus10(l), w4a, sdf[d]);
            sdf[d] = fmaf(softplus10(h), w4b, sdf[d]);
        }
    }
#pragma unroll
    for (int d = 0; d < 4; d++) {
        sdf[d] += __shfl_xor_sync(0xffffffffu, sdf[d], 8);
        sdf[d] += __shfl_xor_sync(0xffffffffu, sdf[d], 16);
    }
    if (q == 0) {
#pragma unroll
        for (int d = 0; d < 4; d++) {
            if (pbase + d < N) out[pbase + d] = sdf[d];
        }
    }
}

extern "C" void kernel_launch(void* const* d_in, const int* in_sizes, int n_in,
                              void* d_out, int out_size)
{
    const float* x    = (const float*)d_in[0];
    const float* grid = (const float*)d_in[1];
    const float* W1   = (const float*)d_in[2];
    const float* W2   = (const float*)d_in[3];
    const float* W3   = (const float*)d_in[4];
    const float* W4   = (const float*)d_in[5];
    float* out = (float*)d_out;

    const int N = in_sizes[0] / 3;

    Meta meta;
    const double Bv = pow(2.0, log2(2048.0 / 16.0) / (double)(N_LEVELS - 1));
    unsigned mask = 0;
    for (int l = 0; l < N_LEVELS; l++) {
        double sc = 16.0 * pow(Bv, (double)l) - 1.0;
        int res = (int)ceil(sc) + 1;
        meta.scale[l] = (float)sc;
        meta.res[l] = res;
        if ((long long)res * res * res > (long long)TBL) mask |= (1u << l);
    }
    meta.hashed_mask = mask;

    prep_weights<<<16, 256>>>(W1, W2, W3, W4);
    encode_kernel<<<(N + 255) / 256, 256>>>(x, grid, N, meta);

    const size_t smem = (size_t)(64 * BLOCK) * sizeof(float);
    mlp_kernel<<<(N + BLOCK - 1) / BLOCK, BLOCK, smem>>>(out, N);
}

// round 9
// speedup vs baseline: 1.6759x; 1.6759x over previous
#include <cuda_runtime.h>
#include <cuda_bf16.h>
#include <math.h>
#include <stdint.h>

#define N_LEVELS 16
#define TBL (1u << 19)
#define BLOCK 128
#define ASTRIDE 68   // 64 + 4 pad floats: conflict-free fragment access

struct Meta {
    float scale[N_LEVELS];
    int   res[N_LEVELS];
    unsigned hashed_mask;
};

// Weights transposed to [k][n], each entry = {tf32_hi, tf32_lo} (float2, 8B)
__device__ float2 g_w1t[32 * 64];
__device__ float2 g_w2t[64 * 64];
__device__ float2 g_w3t[64 * 64];

static __device__ __forceinline__ float tf32r(float x) {
    uint32_t r;
    asm("cvt.rna.tf32.f32 %0, %1;" : "=r"(r) : "f"(x));
    return __uint_as_float(r);
}

static __device__ __forceinline__ float sp10(float v) {
    float t = 10.0f * v;
    float e = __expf(-fabsf(t));
    return (__logf(1.0f + e) + fmaxf(t, 0.0f)) * 0.1f;
}

// D += A(16x8 tf32) x B(8x8 tf32), row.col
static __device__ __forceinline__ void mma8(float* d, const uint32_t* a,
                                            uint32_t b0, uint32_t b1) {
    asm volatile(
        "mma.sync.aligned.m16n8k8.row.col.f32.tf32.tf32.f32 "
        "{%0,%1,%2,%3}, {%4,%5,%6,%7}, {%8,%9}, {%0,%1,%2,%3};"
        : "+f"(d[0]), "+f"(d[1]), "+f"(d[2]), "+f"(d[3])
        : "r"(a[0]), "r"(a[1]), "r"(a[2]), "r"(a[3]), "r"(b0), "r"(b1));
}

__global__ void prep_weights(const float* __restrict__ W1,
                             const float* __restrict__ W2,
                             const float* __restrict__ W3)
{
    const int tid = blockIdx.x * blockDim.x + threadIdx.x;
    const int stride = gridDim.x * blockDim.x;
    for (int idx = tid; idx < 32 * 64; idx += stride) {
        int k = idx >> 6, n = idx & 63;
        float w = W1[n * 32 + k];
        float hi = tf32r(w);
        g_w1t[idx] = make_float2(hi, tf32r(w - hi));
    }
    for (int idx = tid; idx < 64 * 64; idx += stride) {
        int k = idx >> 6, n = idx & 63;
        float w2 = W2[n * 64 + k], w3 = W3[n * 64 + k];
        float h2 = tf32r(w2), h3 = tf32r(w3);
        g_w2t[idx] = make_float2(h2, tf32r(w2 - h2));
        g_w3t[idx] = make_float2(h3, tf32r(w3 - h3));
    }
}

// One layer GEMM: acc[2][8][4] += act[32pts x KT*8] @ W.  Warp-collective.
template <int KT>
static __device__ __forceinline__ void layer_gemm(const float* __restrict__ act,
                                                  const float2* __restrict__ wt,
                                                  int mbase, int g, int tig,
                                                  float acc[2][8][4])
{
#pragma unroll
    for (int m = 0; m < 2; m++)
#pragma unroll
        for (int nt = 0; nt < 8; nt++)
#pragma unroll
            for (int c = 0; c < 4; c++) acc[m][nt][c] = 0.0f;

#pragma unroll
    for (int kt = 0; kt < KT; kt++) {
        uint32_t ahi[2][4], alo[2][4];
#pragma unroll
        for (int m = 0; m < 2; m++) {
            const int r0 = mbase + m * 16 + g;
#pragma unroll
            for (int r = 0; r < 4; r++) {
                const int row = r0 + (r & 1) * 8;
                const int col = kt * 8 + tig + (r >> 1) * 4;
                float a = act[row * ASTRIDE + col];
                float h = tf32r(a);
                ahi[m][r] = __float_as_uint(h);
                alo[m][r] = __float_as_uint(tf32r(a - h));
            }
        }
        const float2* wr0 = wt + (kt * 8 + tig) * 64;
        const float2* wr1 = wt + (kt * 8 + tig + 4) * 64;
#pragma unroll
        for (int nt = 0; nt < 8; nt++) {
            float2 b0 = __ldg(&wr0[nt * 8 + g]);
            float2 b1 = __ldg(&wr1[nt * 8 + g]);
            uint32_t bh0 = __float_as_uint(b0.x), bl0 = __float_as_uint(b0.y);
            uint32_t bh1 = __float_as_uint(b1.x), bl1 = __float_as_uint(b1.y);
#pragma unroll
            for (int m = 0; m < 2; m++) {
                mma8(acc[m][nt], ahi[m], bh0, bh1);
                mma8(acc[m][nt], ahi[m], bl0, bl1);
                mma8(acc[m][nt], alo[m], bh0, bh1);
            }
        }
    }
}

// softplus + write acc back to act rows (warp-private rows)
static __device__ __forceinline__ void layer_store(float* __restrict__ act,
                                                   int mbase, int g, int tig,
                                                   const float acc[2][8][4])
{
#pragma unroll
    for (int m = 0; m < 2; m++) {
        const int r0 = mbase + m * 16 + g;
#pragma unroll
        for (int nt = 0; nt < 8; nt++) {
            const int col = nt * 8 + 2 * tig;
            *(float2*)(act + r0 * ASTRIDE + col) =
                make_float2(sp10(acc[m][nt][0]), sp10(acc[m][nt][1]));
            *(float2*)(act + (r0 + 8) * ASTRIDE + col) =
                make_float2(sp10(acc[m][nt][2]), sp10(acc[m][nt][3]));
        }
    }
}

__global__ void __launch_bounds__(BLOCK)
sdf_kernel(const float* __restrict__ x,
           const float* __restrict__ grid,
           const float* __restrict__ W4,
           float* __restrict__ out,
           int N, Meta meta)
{
    __shared__ float act[BLOCK * ASTRIDE];   // ~34 KB

    const int tid = threadIdx.x;
    const int p = blockIdx.x * BLOCK + tid;

    // ---- Encoding: thread tid -> act row tid (cols 0..31) ----
    if (p < N) {
        const float px = x[p * 3 + 0];
        const float py = x[p * 3 + 1];
        const float pz = x[p * 3 + 2];

        for (int l = 0; l < N_LEVELS; l++) {
            const float s = meta.scale[l];
            const int res = meta.res[l];
            const bool hashed = (meta.hashed_mask >> l) & 1u;

            float fx = fmaf(px, s, 0.5f);
            float fy = fmaf(py, s, 0.5f);
            float fz = fmaf(pz, s, 0.5f);
            float fx0 = floorf(fx), fy0 = floorf(fy), fz0 = floorf(fz);
            float rx = fx - fx0, ry = fy - fy0, rz = fz - fz0;
            int ix = (int)fx0, iy = (int)fy0, iz = (int)fz0;

            const float2* g = (const float2*)grid + (size_t)l * TBL;
            float a0 = 0.0f, a1 = 0.0f;

#pragma unroll
            for (int c = 0; c < 8; c++) {
                const int cx = c & 1, cy = (c >> 1) & 1, cz = (c >> 2) & 1;
                float w = (cx ? rx : 1.0f - rx) *
                          (cy ? ry : 1.0f - ry) *
                          (cz ? rz : 1.0f - rz);
                unsigned idx;
                if (hashed) {
                    unsigned gx = (unsigned)(ix + cx);
                    unsigned gy = (unsigned)(iy + cy);
                    unsigned gz = (unsigned)(iz + cz);
                    idx = (gx * 1u) ^ (gy * 2654435761u) ^ (gz * 805459861u);
                    idx &= (TBL - 1u);
                } else {
                    int gx = min(max(ix + cx, 0), res - 1);
                    int gy = min(max(iy + cy, 0), res - 1);
                    int gz = min(max(iz + cz, 0), res - 1);
                    idx = (unsigned)(gx + res * (gy + res * gz));
                }
                float2 f = __ldg(&g[idx]);
                a0 = fmaf(w, f.x, a0);
                a1 = fmaf(w, f.y, a1);
            }
            *(float2*)(act + tid * ASTRIDE + 2 * l) = make_float2(a0, a1);
        }
    } else {
#pragma unroll
        for (int l = 0; l < N_LEVELS; l++)
            *(float2*)(act + tid * ASTRIDE + 2 * l) = make_float2(0.0f, 0.0f);
    }
    __syncwarp();

    // ---- MLP: warp owns points [mbase, mbase+32) = its own act rows ----
    const int lane  = tid & 31;
    const int g     = lane >> 2;        // groupID
    const int tig   = lane & 3;         // thread-in-group
    const int mbase = (tid >> 5) * 32;

    float acc[2][8][4];

    layer_gemm<4>(act, g_w1t, mbase, g, tig, acc);   // K=32
    layer_store(act, mbase, g, tig, acc);
    __syncwarp();

    layer_gemm<8>(act, g_w2t, mbase, g, tig, acc);   // K=64
    layer_store(act, mbase, g, tig, acc);
    __syncwarp();

    layer_gemm<8>(act, g_w3t, mbase, g, tig, acc);   // K=64

    // ---- Output layer: sdf = softplus(h) . W4, reduce over tig quad ----
    float part[4] = {0.0f, 0.0f, 0.0f, 0.0f};
#pragma unroll
    for (int m = 0; m < 2; m++) {
#pragma unroll
        for (int nt = 0; nt < 8; nt++) {
            const int j = nt * 8 + 2 * tig;
            float w4a = __ldg(&W4[j]);
            float w4b = __ldg(&W4[j + 1]);
            part[m * 2 + 0] = fmaf(sp10(acc[m][nt][0]), w4a,
                             fmaf(sp10(acc[m][nt][1]), w4b, part[m * 2 + 0]));
            part[m * 2 + 1] = fmaf(sp10(acc[m][nt][2]), w4a,
                             fmaf(sp10(acc[m][nt][3]), w4b, part[m * 2 + 1]));
        }
    }
#pragma unroll
    for (int d = 0; d < 4; d++) {
        part[d] += __shfl_xor_sync(0xffffffffu, part[d], 1);
        part[d] += __shfl_xor_sync(0xffffffffu, part[d], 2);
    }
    if (tig == 0) {
        const int base = blockIdx.x * BLOCK + mbase;
#pragma unroll
        for (int m = 0; m < 2; m++) {
            int p0 = base + m * 16 + g;       // rows g and g+8 of this m-tile
            if (p0 < N) out[p0] = part[m * 2 + 0];
            if (p0 + 8 < N) out[p0 + 8] = part[m * 2 + 1];
        }
    }
}

extern "C" void kernel_launch(void* const* d_in, const int* in_sizes, int n_in,
                              void* d_out, int out_size)
{
    const float* x    = (const float*)d_in[0];
    const float* grid = (const float*)d_in[1];
    const float* W1   = (const float*)d_in[2];
    const float* W2   = (const float*)d_in[3];
    const float* W3   = (const float*)d_in[4];
    const float* W4   = (const float*)d_in[5];
    float* out = (float*)d_out;

    const int N = in_sizes[0] / 3;

    Meta meta;
    const double Bv = pow(2.0, log2(2048.0 / 16.0) / (double)(N_LEVELS - 1));
    unsigned mask = 0;
    for (int l = 0; l < N_LEVELS; l++) {
        double sc = 16.0 * pow(Bv, (double)l) - 1.0;
        int res = (int)ceil(sc) + 1;
        meta.scale[l] = (float)sc;
        meta.res[l] = res;
        if ((long long)res * res * res > (long long)TBL) mask |= (1u << l);
    }
    meta.hashed_mask = mask;

    prep_weights<<<16, 256>>>(W1, W2, W3);

    const int blocks = (N + BLOCK - 1) / BLOCK;
    sdf_kernel<<<blocks, BLOCK>>>(x, grid, W4, out, N, meta);
}